// round 4
// baseline (speedup 1.0000x reference)
#include <cuda_runtime.h>

#define N_ROWS 65536
#define D 64
#define R 256
#define DV 64
#define NORM 0.35355339059327379f   // 64^-0.25
#define RATIO 0.0625f               // 256^-0.5

#define ROWS_K 128
#define KTILES (N_ROWS / ROWS_K)    // 512
#define KBLOCKS 148
#define ROWS_Q 64
#define QTILES (N_ROWS / ROWS_Q)    // 1024

#define QH_STRIDE (R + 4)

typedef unsigned long long u64;

// ---- packed f32x2 helpers (Blackwell FFMA2 pipe; ptxas never auto-emits) ----
__device__ __forceinline__ u64 ffma2(u64 a, u64 b, u64 c) {
    u64 d;
    asm("fma.rn.f32x2 %0, %1, %2, %3;" : "=l"(d) : "l"(a), "l"(b), "l"(c));
    return d;
}
__device__ __forceinline__ u64 fmul2(u64 a, u64 b) {
    u64 d;
    asm("mul.rn.f32x2 %0, %1, %2;" : "=l"(d) : "l"(a), "l"(b));
    return d;
}
__device__ __forceinline__ u64 pack2(float x, float y) {
    u64 r;
    asm("mov.b64 %0, {%1, %2};" : "=l"(r) : "f"(x), "f"(y));
    return r;
}
__device__ __forceinline__ float2 unpack2(u64 a) {
    float x, y;
    asm("mov.b64 {%0, %1}, %2;" : "=f"(x), "=f"(y) : "l"(a));
    return make_float2(x, y);
}

// scratch (allocation-free rule: device globals)
__device__ float g_z[R * DV];
__device__ float g_ksum[R];

__global__ void zero_kernel() {
    int t = blockIdx.x * blockDim.x + threadIdx.x;
    if (t < R * DV) g_z[t] = 0.0f;
    if (t < R) g_ksum[t] = 0.0f;
}

// ---------------- K side: z = k_hat^T @ v, ksum = sum_i k_hat[i,:] -------------
__global__ __launch_bounds__(256, 1) void kside_kernel(
    const float* __restrict__ kin, const float* __restrict__ vin,
    const float* __restrict__ proj)
{
    extern __shared__ float smem[];
    float* kn = smem;                      // ROWS_K * D
    float* vs = kn + ROWS_K * D;           // ROWS_K * DV
    float* sn = vs + ROWS_K * DV;          // ROWS_K

    const int t = threadIdx.x;             // 0..255 <-> feature r

    // projection row, packed pairs (32 x u64 = 64 floats)
    u64 pp[D / 2];
    {
        const ulonglong2* pg = reinterpret_cast<const ulonglong2*>(&proj[t * D]);
#pragma unroll
        for (int j = 0; j < D / 4; j++) {
            ulonglong2 w = pg[j];
            pp[2 * j] = w.x; pp[2 * j + 1] = w.y;
        }
    }

    u64 zacc2[DV / 2];
#pragma unroll
    for (int c = 0; c < DV / 2; c++) zacc2[c] = 0ull;
    float ksacc = 0.0f;

    for (int tile = blockIdx.x; tile < KTILES; tile += gridDim.x) {
        __syncthreads();
        const float4* kb = reinterpret_cast<const float4*>(kin + (size_t)tile * ROWS_K * D);
        const float4* vb = reinterpret_cast<const float4*>(vin + (size_t)tile * ROWS_K * DV);
#pragma unroll
        for (int m = 0; m < (ROWS_K * D / 4) / 256; m++) {   // 8 iters
            int idx = t + 256 * m;
            float4 a = kb[idx];
            a.x *= NORM; a.y *= NORM; a.z *= NORM; a.w *= NORM;
            *reinterpret_cast<float4*>(&kn[idx * 4]) = a;
            float ps = a.x * a.x + a.y * a.y + a.z * a.z + a.w * a.w;
#pragma unroll
            for (int s = 8; s >= 1; s >>= 1)
                ps += __shfl_xor_sync(0xffffffffu, ps, s);
            if ((t & 15) == 0) sn[idx >> 4] = ps;
            *reinterpret_cast<float4*>(&vs[idx * 4]) = vb[idx];
        }
        __syncthreads();

        for (int i = 0; i < ROWS_K; i++) {
            // dash = kn[i,:] . p  — packed, 2 accumulators to cover FMA latency
            u64 da = 0ull, db = 0ull;
            const ulonglong2* kr = reinterpret_cast<const ulonglong2*>(&kn[i * D]);
#pragma unroll
            for (int j = 0; j < D / 4; j++) {
                ulonglong2 w = kr[j];
                da = ffma2(w.x, pp[2 * j], da);
                db = ffma2(w.y, pp[2 * j + 1], db);
            }
            float2 fa = unpack2(da), fb = unpack2(db);
            float dash = (fa.x + fa.y) + (fb.x + fb.y);

            float kh = RATIO * __expf(dash - 0.5f * sn[i]);
            ksacc += kh;
            u64 kh2 = pack2(kh, kh);

            const ulonglong2* vr = reinterpret_cast<const ulonglong2*>(&vs[i * DV]);
#pragma unroll
            for (int c = 0; c < DV / 4; c++) {
                ulonglong2 w = vr[c];
                zacc2[2 * c]     = ffma2(kh2, w.x, zacc2[2 * c]);
                zacc2[2 * c + 1] = ffma2(kh2, w.y, zacc2[2 * c + 1]);
            }
        }
    }

    atomicAdd(&g_ksum[t], ksacc);
#pragma unroll
    for (int c = 0; c < DV / 2; c++) {
        float2 f = unpack2(zacc2[c]);
        atomicAdd(&g_z[t * DV + 2 * c],     f.x);
        atomicAdd(&g_z[t * DV + 2 * c + 1], f.y);
    }
}

// ---------------- Q side: out = (q_hat @ z) / (q_hat . ksum) ------------------
__global__ __launch_bounds__(256, 1) void qside_kernel(
    const float* __restrict__ qin, const float* __restrict__ proj,
    float* __restrict__ out)
{
    extern __shared__ float smem[];
    float* zsh  = smem;                          // R*DV
    float* qh   = zsh + R * DV;                  // ROWS_Q*QH_STRIDE
    float* qn   = qh + ROWS_Q * QH_STRIDE;       // ROWS_Q*D
    float* sn   = qn + ROWS_Q * D;               // ROWS_Q
    float* ks   = sn + ROWS_Q;                   // R
    float* dinv = ks + R;                        // ROWS_Q

    const int t = threadIdx.x;

    u64 pp[D / 2];
    {
        const ulonglong2* pg = reinterpret_cast<const ulonglong2*>(&proj[t * D]);
#pragma unroll
        for (int j = 0; j < D / 4; j++) {
            ulonglong2 w = pg[j];
            pp[2 * j] = w.x; pp[2 * j + 1] = w.y;
        }
    }

    // stage z + ksum into shared
#pragma unroll
    for (int m = 0; m < (R * DV / 4) / 256; m++) {   // 16 iters
        int idx = t + 256 * m;
        *reinterpret_cast<float4*>(&zsh[idx * 4]) =
            *reinterpret_cast<const float4*>(&g_z[idx * 4]);
    }
    ks[t] = g_ksum[t];

    const int tile = blockIdx.x;
    const float4* qb = reinterpret_cast<const float4*>(qin + (size_t)tile * ROWS_Q * D);
#pragma unroll
    for (int m = 0; m < (ROWS_Q * D / 4) / 256; m++) {  // 4 iters
        int idx = t + 256 * m;
        float4 a = qb[idx];
        a.x *= NORM; a.y *= NORM; a.z *= NORM; a.w *= NORM;
        *reinterpret_cast<float4*>(&qn[idx * 4]) = a;
        float ps = a.x * a.x + a.y * a.y + a.z * a.z + a.w * a.w;
#pragma unroll
        for (int s = 8; s >= 1; s >>= 1)
            ps += __shfl_xor_sync(0xffffffffu, ps, s);
        if ((t & 15) == 0) sn[idx >> 4] = ps;
    }
    __syncthreads();

    // phase 1: qh[i][t] = ratio * exp(dash - 0.5*sn)
    for (int i = 0; i < ROWS_Q; i++) {
        u64 da = 0ull, db = 0ull;
        const ulonglong2* qr = reinterpret_cast<const ulonglong2*>(&qn[i * D]);
#pragma unroll
        for (int j = 0; j < D / 4; j++) {
            ulonglong2 w = qr[j];
            da = ffma2(w.x, pp[2 * j], da);
            db = ffma2(w.y, pp[2 * j + 1], db);
        }
        float2 fa = unpack2(da), fb = unpack2(db);
        float dash = (fa.x + fa.y) + (fb.x + fb.y);
        qh[i * QH_STRIDE + t] = RATIO * __expf(dash - 0.5f * sn[i]);
    }
    __syncthreads();

    // denominators: warp w -> rows w*8 .. w*8+7
    {
        int w = t >> 5, l = t & 31;
#pragma unroll
        for (int ii = 0; ii < 8; ii++) {
            int i = w * 8 + ii;
            float s = 0.0f;
#pragma unroll
            for (int kk = 0; kk < R / 32; kk++)
                s += qh[i * QH_STRIDE + l + 32 * kk] * ks[l + 32 * kk];
#pragma unroll
            for (int sd = 16; sd >= 1; sd >>= 1)
                s += __shfl_xor_sync(0xffffffffu, s, sd);
            if (l == 0) dinv[i] = 1.0f / s;
        }
    }
    __syncthreads();

    // phase 2: 4x4 register-tiled GEMM qh[64x256] @ zsh[256x64], packed columns
    {
        const int bc = t & 15;       // column block
        const int bi = t >> 4;       // row block
        const int i0 = bi * 4;
        const int c0 = bc * 4;
        u64 acc[4][2];
#pragma unroll
        for (int a = 0; a < 4; a++) { acc[a][0] = 0ull; acc[a][1] = 0ull; }

#pragma unroll 4
        for (int r = 0; r < R; r++) {
            ulonglong2 zv = *reinterpret_cast<const ulonglong2*>(&zsh[r * DV + c0]);
            u64 q0 = pack2(qh[(i0 + 0) * QH_STRIDE + r], qh[(i0 + 0) * QH_STRIDE + r]);
            u64 q1 = pack2(qh[(i0 + 1) * QH_STRIDE + r], qh[(i0 + 1) * QH_STRIDE + r]);
            u64 q2 = pack2(qh[(i0 + 2) * QH_STRIDE + r], qh[(i0 + 2) * QH_STRIDE + r]);
            u64 q3 = pack2(qh[(i0 + 3) * QH_STRIDE + r], qh[(i0 + 3) * QH_STRIDE + r]);
            acc[0][0] = ffma2(q0, zv.x, acc[0][0]); acc[0][1] = ffma2(q0, zv.y, acc[0][1]);
            acc[1][0] = ffma2(q1, zv.x, acc[1][0]); acc[1][1] = ffma2(q1, zv.y, acc[1][1]);
            acc[2][0] = ffma2(q2, zv.x, acc[2][0]); acc[2][1] = ffma2(q2, zv.y, acc[2][1]);
            acc[3][0] = ffma2(q3, zv.x, acc[3][0]); acc[3][1] = ffma2(q3, zv.y, acc[3][1]);
        }

        float* ob = out + (size_t)tile * ROWS_Q * DV;
#pragma unroll
        for (int a = 0; a < 4; a++) {
            float di = dinv[i0 + a];
            u64 d2 = pack2(di, di);
            ulonglong2 o;
            o.x = fmul2(acc[a][0], d2);
            o.y = fmul2(acc[a][1], d2);
            *reinterpret_cast<ulonglong2*>(&ob[(i0 + a) * DV + c0]) = o;
        }
    }
}

extern "C" void kernel_launch(void* const* d_in, const int* in_sizes, int n_in,
                              void* d_out, int out_size) {
    const float* q = (const float*)d_in[0];
    const float* k = (const float*)d_in[1];
    const float* v = (const float*)d_in[2];
    const float* P = (const float*)d_in[3];
    float* out = (float*)d_out;
    (void)in_sizes; (void)n_in; (void)out_size;

    const int ksmem = (ROWS_K * D + ROWS_K * DV + ROWS_K) * (int)sizeof(float);
    const int qsmem = (R * DV + ROWS_Q * QH_STRIDE + ROWS_Q * D + ROWS_Q + R + ROWS_Q)
                      * (int)sizeof(float);

    cudaFuncSetAttribute(kside_kernel, cudaFuncAttributeMaxDynamicSharedMemorySize, ksmem);
    cudaFuncSetAttribute(qside_kernel, cudaFuncAttributeMaxDynamicSharedMemorySize, qsmem);

    zero_kernel<<<64, 256>>>();
    kside_kernel<<<KBLOCKS, 256, ksmem>>>(k, v, P);
    qside_kernel<<<QTILES, 256, qsmem>>>(q, P, out);
}

// round 5
// speedup vs baseline: 1.0149x; 1.0149x over previous
#include <cuda_runtime.h>

#define N_ROWS 65536
#define D 64
#define R 256
#define DV 64
#define NORM 0.35355339059327379f   // 64^-0.25
#define RATIO 0.0625f               // 256^-0.5

#define ROWS_K 128
#define KTILES (N_ROWS / ROWS_K)    // 512
#define KBLOCKS 148
#define ROWS_Q 64
#define QTILES (N_ROWS / ROWS_Q)    // 1024

#define QH_STRIDE (R + 4)

typedef unsigned long long u64;

// ---- packed f32x2 helpers (Blackwell FFMA2 pipe; ptxas never auto-emits) ----
__device__ __forceinline__ u64 ffma2(u64 a, u64 b, u64 c) {
    u64 d;
    asm("fma.rn.f32x2 %0, %1, %2, %3;" : "=l"(d) : "l"(a), "l"(b), "l"(c));
    return d;
}
__device__ __forceinline__ u64 fmul2(u64 a, u64 b) {
    u64 d;
    asm("mul.rn.f32x2 %0, %1, %2;" : "=l"(d) : "l"(a), "l"(b));
    return d;
}
__device__ __forceinline__ u64 pack2(float x, float y) {
    u64 r;
    asm("mov.b64 %0, {%1, %2};" : "=l"(r) : "f"(x), "f"(y));
    return r;
}
__device__ __forceinline__ float2 unpack2(u64 a) {
    float x, y;
    asm("mov.b64 {%0, %1}, %2;" : "=f"(x), "=f"(y) : "l"(a));
    return make_float2(x, y);
}

// scratch (allocation-free rule: device globals)
__device__ float g_z[R * DV];
__device__ float g_ksum[R];

__global__ void zero_kernel() {
    int t = blockIdx.x * blockDim.x + threadIdx.x;
    if (t < R * DV) g_z[t] = 0.0f;
    if (t < R) g_ksum[t] = 0.0f;
}

// ---------------- K side: z = k_hat^T @ v, ksum = sum_i k_hat[i,:] -------------
__global__ __launch_bounds__(256, 1) void kside_kernel(
    const float* __restrict__ kin, const float* __restrict__ vin,
    const float* __restrict__ proj)
{
    extern __shared__ float smem[];
    float* kn = smem;                      // ROWS_K * D
    float* vs = kn + ROWS_K * D;           // ROWS_K * DV
    float* sn = vs + ROWS_K * DV;          // ROWS_K

    const int t = threadIdx.x;             // 0..255 <-> feature r

    // projection row, packed pairs (32 x u64 = 64 floats)
    u64 pp[D / 2];
    {
        const ulonglong2* pg = reinterpret_cast<const ulonglong2*>(&proj[t * D]);
#pragma unroll
        for (int j = 0; j < D / 4; j++) {
            ulonglong2 w = pg[j];
            pp[2 * j] = w.x; pp[2 * j + 1] = w.y;
        }
    }

    u64 zacc2[DV / 2];
#pragma unroll
    for (int c = 0; c < DV / 2; c++) zacc2[c] = 0ull;
    float ksacc = 0.0f;

    for (int tile = blockIdx.x; tile < KTILES; tile += gridDim.x) {
        __syncthreads();
        const float4* kb = reinterpret_cast<const float4*>(kin + (size_t)tile * ROWS_K * D);
        const float4* vb = reinterpret_cast<const float4*>(vin + (size_t)tile * ROWS_K * DV);
#pragma unroll
        for (int m = 0; m < (ROWS_K * D / 4) / 256; m++) {   // 8 iters
            int idx = t + 256 * m;
            float4 a = kb[idx];
            a.x *= NORM; a.y *= NORM; a.z *= NORM; a.w *= NORM;
            *reinterpret_cast<float4*>(&kn[idx * 4]) = a;
            float ps = a.x * a.x + a.y * a.y + a.z * a.z + a.w * a.w;
#pragma unroll
            for (int s = 8; s >= 1; s >>= 1)
                ps += __shfl_xor_sync(0xffffffffu, ps, s);
            if ((t & 15) == 0) sn[idx >> 4] = ps;
            *reinterpret_cast<float4*>(&vs[idx * 4]) = vb[idx];
        }
        __syncthreads();

        for (int i = 0; i < ROWS_K; i++) {
            // dash = kn[i,:] . p  — packed, 2 accumulators to cover FMA latency
            u64 da = 0ull, db = 0ull;
            const ulonglong2* kr = reinterpret_cast<const ulonglong2*>(&kn[i * D]);
#pragma unroll
            for (int j = 0; j < D / 4; j++) {
                ulonglong2 w = kr[j];
                da = ffma2(w.x, pp[2 * j], da);
                db = ffma2(w.y, pp[2 * j + 1], db);
            }
            float2 fa = unpack2(da), fb = unpack2(db);
            float dash = (fa.x + fa.y) + (fb.x + fb.y);

            float kh = RATIO * __expf(dash - 0.5f * sn[i]);
            ksacc += kh;
            u64 kh2 = pack2(kh, kh);

            const ulonglong2* vr = reinterpret_cast<const ulonglong2*>(&vs[i * DV]);
#pragma unroll
            for (int c = 0; c < DV / 4; c++) {
                ulonglong2 w = vr[c];
                zacc2[2 * c]     = ffma2(kh2, w.x, zacc2[2 * c]);
                zacc2[2 * c + 1] = ffma2(kh2, w.y, zacc2[2 * c + 1]);
            }
        }
    }

    atomicAdd(&g_ksum[t], ksacc);
#pragma unroll
    for (int c = 0; c < DV / 2; c++) {
        float2 f = unpack2(zacc2[c]);
        atomicAdd(&g_z[t * DV + 2 * c],     f.x);
        atomicAdd(&g_z[t * DV + 2 * c + 1], f.y);
    }
}

// ---------------- Q side: out = (q_hat @ z) / (q_hat . ksum) ------------------
__global__ __launch_bounds__(256, 1) void qside_kernel(
    const float* __restrict__ qin, const float* __restrict__ proj,
    float* __restrict__ out)
{
    extern __shared__ float smem[];
    float* zsh  = smem;                          // R*DV
    float* qh   = zsh + R * DV;                  // ROWS_Q*QH_STRIDE
    float* qn   = qh + ROWS_Q * QH_STRIDE;       // ROWS_Q*D
    float* sn   = qn + ROWS_Q * D;               // ROWS_Q
    float* ks   = sn + ROWS_Q;                   // R
    float* dinv = ks + R;                        // ROWS_Q

    const int t = threadIdx.x;

    u64 pp[D / 2];
    {
        const ulonglong2* pg = reinterpret_cast<const ulonglong2*>(&proj[t * D]);
#pragma unroll
        for (int j = 0; j < D / 4; j++) {
            ulonglong2 w = pg[j];
            pp[2 * j] = w.x; pp[2 * j + 1] = w.y;
        }
    }

    // stage z + ksum into shared
#pragma unroll
    for (int m = 0; m < (R * DV / 4) / 256; m++) {   // 16 iters
        int idx = t + 256 * m;
        *reinterpret_cast<float4*>(&zsh[idx * 4]) =
            *reinterpret_cast<const float4*>(&g_z[idx * 4]);
    }
    ks[t] = g_ksum[t];

    const int tile = blockIdx.x;
    const float4* qb = reinterpret_cast<const float4*>(qin + (size_t)tile * ROWS_Q * D);
#pragma unroll
    for (int m = 0; m < (ROWS_Q * D / 4) / 256; m++) {  // 4 iters
        int idx = t + 256 * m;
        float4 a = qb[idx];
        a.x *= NORM; a.y *= NORM; a.z *= NORM; a.w *= NORM;
        *reinterpret_cast<float4*>(&qn[idx * 4]) = a;
        float ps = a.x * a.x + a.y * a.y + a.z * a.z + a.w * a.w;
#pragma unroll
        for (int s = 8; s >= 1; s >>= 1)
            ps += __shfl_xor_sync(0xffffffffu, ps, s);
        if ((t & 15) == 0) sn[idx >> 4] = ps;
    }
    __syncthreads();

    // phase 1: qh[i][t] = ratio * exp(dash - 0.5*sn)
    for (int i = 0; i < ROWS_Q; i++) {
        u64 da = 0ull, db = 0ull;
        const ulonglong2* qr = reinterpret_cast<const ulonglong2*>(&qn[i * D]);
#pragma unroll
        for (int j = 0; j < D / 4; j++) {
            ulonglong2 w = qr[j];
            da = ffma2(w.x, pp[2 * j], da);
            db = ffma2(w.y, pp[2 * j + 1], db);
        }
        float2 fa = unpack2(da), fb = unpack2(db);
        float dash = (fa.x + fa.y) + (fb.x + fb.y);
        qh[i * QH_STRIDE + t] = RATIO * __expf(dash - 0.5f * sn[i]);
    }
    __syncthreads();

    // denominators: warp w -> rows w*8 .. w*8+7
    {
        int w = t >> 5, l = t & 31;
#pragma unroll
        for (int ii = 0; ii < 8; ii++) {
            int i = w * 8 + ii;
            float s = 0.0f;
#pragma unroll
            for (int kk = 0; kk < R / 32; kk++)
                s += qh[i * QH_STRIDE + l + 32 * kk] * ks[l + 32 * kk];
#pragma unroll
            for (int sd = 16; sd >= 1; sd >>= 1)
                s += __shfl_xor_sync(0xffffffffu, s, sd);
            if (l == 0) dinv[i] = 1.0f / s;
        }
    }
    __syncthreads();

    // phase 2: 4x4 register-tiled GEMM qh[64x256] @ zsh[256x64], packed columns
    {
        const int bc = t & 15;       // column block
        const int bi = t >> 4;       // row block
        const int i0 = bi * 4;
        const int c0 = bc * 4;
        u64 acc[4][2];
#pragma unroll
        for (int a = 0; a < 4; a++) { acc[a][0] = 0ull; acc[a][1] = 0ull; }

#pragma unroll 4
        for (int r = 0; r < R; r++) {
            ulonglong2 zv = *reinterpret_cast<const ulonglong2*>(&zsh[r * DV + c0]);
            u64 q0 = pack2(qh[(i0 + 0) * QH_STRIDE + r], qh[(i0 + 0) * QH_STRIDE + r]);
            u64 q1 = pack2(qh[(i0 + 1) * QH_STRIDE + r], qh[(i0 + 1) * QH_STRIDE + r]);
            u64 q2 = pack2(qh[(i0 + 2) * QH_STRIDE + r], qh[(i0 + 2) * QH_STRIDE + r]);
            u64 q3 = pack2(qh[(i0 + 3) * QH_STRIDE + r], qh[(i0 + 3) * QH_STRIDE + r]);
            acc[0][0] = ffma2(q0, zv.x, acc[0][0]); acc[0][1] = ffma2(q0, zv.y, acc[0][1]);
            acc[1][0] = ffma2(q1, zv.x, acc[1][0]); acc[1][1] = ffma2(q1, zv.y, acc[1][1]);
            acc[2][0] = ffma2(q2, zv.x, acc[2][0]); acc[2][1] = ffma2(q2, zv.y, acc[2][1]);
            acc[3][0] = ffma2(q3, zv.x, acc[3][0]); acc[3][1] = ffma2(q3, zv.y, acc[3][1]);
        }

        float* ob = out + (size_t)tile * ROWS_Q * DV;
#pragma unroll
        for (int a = 0; a < 4; a++) {
            float di = dinv[i0 + a];
            u64 d2 = pack2(di, di);
            ulonglong2 o;
            o.x = fmul2(acc[a][0], d2);
            o.y = fmul2(acc[a][1], d2);
            *reinterpret_cast<ulonglong2*>(&ob[(i0 + a) * DV + c0]) = o;
        }
    }
}

extern "C" void kernel_launch(void* const* d_in, const int* in_sizes, int n_in,
                              void* d_out, int out_size) {
    const float* q = (const float*)d_in[0];
    const float* k = (const float*)d_in[1];
    const float* v = (const float*)d_in[2];
    const float* P = (const float*)d_in[3];
    float* out = (float*)d_out;
    (void)in_sizes; (void)n_in; (void)out_size;

    const int ksmem = (ROWS_K * D + ROWS_K * DV + ROWS_K) * (int)sizeof(float);
    const int qsmem = (R * DV + ROWS_Q * QH_STRIDE + ROWS_Q * D + ROWS_Q + R + ROWS_Q)
                      * (int)sizeof(float);

    cudaFuncSetAttribute(kside_kernel, cudaFuncAttributeMaxDynamicSharedMemorySize, ksmem);
    cudaFuncSetAttribute(qside_kernel, cudaFuncAttributeMaxDynamicSharedMemorySize, qsmem);

    zero_kernel<<<64, 256>>>();
    kside_kernel<<<KBLOCKS, 256, ksmem>>>(k, v, P);
    qside_kernel<<<QTILES, 256, qsmem>>>(q, P, out);
}

// round 7
// speedup vs baseline: 1.9628x; 1.9341x over previous
#include <cuda_runtime.h>
#include <cuda_bf16.h>
#include <cstdint>

typedef unsigned int u32;

#define NORM 0.35355339059327379f   // 64^-0.25
#define RATIO 0.0625f               // 256^-0.5
#define TILE 128
#define NTILES 512
#define KBLOCKS 148

// scratch (allocation-free rule)
__device__ float g_zT[65 * 256];               // [n(0..64)][feat]; row 64 = ksum
__device__ __nv_bfloat16 g_zbh[72 * 256];      // bf16 split of zT (rows 65..71 = 0)
__device__ __nv_bfloat16 g_zbl[72 * 256];

// ---------------- helpers ----------------
__device__ __forceinline__ u32 smem_u32(const void* p) {
    u32 a; asm("{ .reg .u64 t; cvta.to.shared.u64 t, %1; cvt.u32.u64 %0, t; }" : "=r"(a) : "l"(p)); return a;
}
__device__ __forceinline__ void mma_bf16(float* d, const u32* a, const u32* b) {
    asm volatile(
        "mma.sync.aligned.m16n8k16.row.col.f32.bf16.bf16.f32 "
        "{%0,%1,%2,%3}, {%4,%5,%6,%7}, {%8,%9}, {%0,%1,%2,%3};"
        : "+f"(d[0]), "+f"(d[1]), "+f"(d[2]), "+f"(d[3])
        : "r"(a[0]), "r"(a[1]), "r"(a[2]), "r"(a[3]), "r"(b[0]), "r"(b[1]));
}
__device__ __forceinline__ void ldmx2t(u32& r0, u32& r1, u32 addr) {
    asm volatile("ldmatrix.sync.aligned.m8n8.x2.trans.shared.b16 {%0,%1}, [%2];"
        : "=r"(r0), "=r"(r1) : "r"(addr));
}
__device__ __forceinline__ void split2(float x, float y, u32& h, u32& l) {
    __nv_bfloat162 hh = __floats2bfloat162_rn(x, y);
    float2 hf = __bfloat1622float2(hh);
    __nv_bfloat162 ll = __floats2bfloat162_rn(x - hf.x, y - hf.y);
    h = *reinterpret_cast<u32*>(&hh);
    l = *reinterpret_cast<u32*>(&ll);
}
__device__ __forceinline__ void split1(float x, uint16_t& h, uint16_t& l) {
    __nv_bfloat16 bh = __float2bfloat16(x);
    h = __bfloat16_as_ushort(bh);
    l = __bfloat16_as_ushort(__float2bfloat16(x - __bfloat162float(bh)));
}

// stage [nrows x 64] fp32 (RAW, no norm) -> bf16 hi/lo, row-major stride bytes.
// If sn != nullptr, also writes per-row sum of squares (raw).
__device__ __forceinline__ void stage64(char* dh, char* dl, const float* src,
                                        int nrows, int stride, float* sn, int tid) {
    const float4* sp = reinterpret_cast<const float4*>(src);
    int total = nrows * 16;
    for (int idx = tid; idx < total; idx += 256) {
        int row = idx >> 4, c4 = idx & 15;
        float4 f = sp[idx];
        if (sn) {
            float ps = f.x * f.x + f.y * f.y + f.z * f.z + f.w * f.w;
#pragma unroll
            for (int s = 8; s >= 1; s >>= 1) ps += __shfl_xor_sync(0xffffffffu, ps, s);
            if ((tid & 15) == 0) sn[row] = ps;
        }
        u32 h0, l0, h1, l1;
        split2(f.x, f.y, h0, l0);
        split2(f.z, f.w, h1, l1);
        *(uint2*)(dh + row * stride + c4 * 8) = make_uint2(h0, h1);
        *(uint2*)(dl + row * stride + c4 * 8) = make_uint2(l0, l1);
    }
}

__global__ void zero_kernel() {
    int t = blockIdx.x * blockDim.x + threadIdx.x;
    if (t < 65 * 256) g_zT[t] = 0.0f;
}
__global__ void zsplit_kernel() {
    int t = blockIdx.x * blockDim.x + threadIdx.x;
    if (t >= 72 * 256) return;
    int n = t >> 8;
    float x = (n < 65) ? g_zT[t] : 0.0f;
    __nv_bfloat16 h = __float2bfloat16(x);
    g_zbh[t] = h;
    g_zbl[t] = __float2bfloat16(x - __bfloat162float(h));
}

// ======================= kside =======================
// SMEM (bytes): Pt hi/lo [256][136], kn hi/lo [128][136],
//               k_hat half hi/lo [128][272], vT hi/lo [80][264], sn[128]
#define KS_PTH 0
#define KS_PTL 34816
#define KS_KNH 69632
#define KS_KNL 87040
#define KS_KHH 104448
#define KS_KHL 139264
#define KS_VTH 174080
#define KS_VTL 195200
#define KS_SN  216320
#define KSMEM  216832

__global__ __launch_bounds__(256, 1) void kside_kernel(
    const float* __restrict__ kin, const float* __restrict__ vin,
    const float* __restrict__ proj)
{
    extern __shared__ char sm[];
    const int tid = threadIdx.x;
    const int lane = tid & 31, w = tid >> 5;
    const int g = lane >> 2, tg = lane & 3;
    float* sn = reinterpret_cast<float*>(sm + KS_SN);
    const u32 khh_u = smem_u32(sm) + KS_KHH;
    const u32 khl_u = smem_u32(sm) + KS_KHL;

    stage64(sm + KS_PTH, sm + KS_PTL, proj, 256, 136, nullptr, tid);
    // vT constant rows: n=64 -> ones, n=65..79 -> zero (set once)
    for (int i = tid; i < 16 * 128; i += 256) {
        int n = 64 + (i >> 7), k = i & 127;
        uint16_t hv = (n == 64) ? (uint16_t)0x3F80 : (uint16_t)0;
        *(uint16_t*)(sm + KS_VTH + n * 264 + k * 2) = hv;
        *(uint16_t*)(sm + KS_VTL + n * 264 + k * 2) = 0;
    }

    float zacc[5][4][4];
#pragma unroll
    for (int m = 0; m < 5; m++)
#pragma unroll
        for (int j = 0; j < 4; j++)
#pragma unroll
            for (int r = 0; r < 4; r++) zacc[m][j][r] = 0.0f;

    for (int tile = blockIdx.x; tile < NTILES; tile += KBLOCKS) {
        __syncthreads();   // prev z-mma / dash readers done before restage
        stage64(sm + KS_KNH, sm + KS_KNL, kin + (size_t)tile * TILE * 64, 128, 136, sn, tid);
        {   // stage v transposed: vT[n=col][krow]
            const float4* sp = reinterpret_cast<const float4*>(vin + (size_t)tile * TILE * 64);
            for (int idx = tid; idx < 2048; idx += 256) {
                int row = idx >> 4, c4 = idx & 15;
                float4 f = sp[idx];
                float vv[4] = {f.x, f.y, f.z, f.w};
#pragma unroll
                for (int j = 0; j < 4; j++) {
                    uint16_t h, l; split1(vv[j], h, l);
                    int n = c4 * 4 + j;
                    *(uint16_t*)(sm + KS_VTH + n * 264 + row * 2) = h;
                    *(uint16_t*)(sm + KS_VTL + n * 264 + row * 2) = l;
                }
            }
        }
        __syncthreads();

        for (int h = 0; h < 2; h++) {
            // ---- dash: D[16 rows][128 feats] per warp ----
            float dD[16][4];
#pragma unroll
            for (int nt = 0; nt < 16; nt++)
#pragma unroll
                for (int r = 0; r < 4; r++) dD[nt][r] = 0.0f;
#pragma unroll
            for (int ks = 0; ks < 4; ks++) {
                u32 ab = (u32)((w * 16 + g) * 136 + ks * 32 + tg * 4);
                u32 ah[4] = { *(u32*)(sm + KS_KNH + ab),       *(u32*)(sm + KS_KNH + ab + 8 * 136),
                              *(u32*)(sm + KS_KNH + ab + 16),  *(u32*)(sm + KS_KNH + ab + 8 * 136 + 16) };
                u32 al[4] = { *(u32*)(sm + KS_KNL + ab),       *(u32*)(sm + KS_KNL + ab + 8 * 136),
                              *(u32*)(sm + KS_KNL + ab + 16),  *(u32*)(sm + KS_KNL + ab + 8 * 136 + 16) };
#pragma unroll
                for (int nt = 0; nt < 16; nt++) {
                    u32 bb = (u32)((h * 128 + nt * 8 + g) * 136 + ks * 32 + tg * 4);
                    u32 bh[2] = { *(u32*)(sm + KS_PTH + bb), *(u32*)(sm + KS_PTH + bb + 16) };
                    u32 bl[2] = { *(u32*)(sm + KS_PTL + bb), *(u32*)(sm + KS_PTL + bb + 16) };
                    mma_bf16(dD[nt], ah, bh);
                    mma_bf16(dD[nt], ah, bl);
                    mma_bf16(dD[nt], al, bh);
                }
            }
            // ---- epilogue: exp, split, store k_hat[krow][feat-in-half] ----
            {
                float s0 = sn[w * 16 + g], s1 = sn[w * 16 + 8 + g];
#pragma unroll
                for (int nt = 0; nt < 16; nt++) {
                    float e0 = RATIO * __expf(NORM * dD[nt][0] - 0.0625f * s0);
                    float e1 = RATIO * __expf(NORM * dD[nt][1] - 0.0625f * s0);
                    float e2 = RATIO * __expf(NORM * dD[nt][2] - 0.0625f * s1);
                    float e3 = RATIO * __expf(NORM * dD[nt][3] - 0.0625f * s1);
                    u32 h01, l01, h23, l23;
                    split2(e0, e1, h01, l01);
                    split2(e2, e3, h23, l23);
                    u32 o0 = (u32)((w * 16 + g) * 272 + (nt * 8 + tg * 2) * 2);
                    u32 o1 = (u32)((w * 16 + 8 + g) * 272 + (nt * 8 + tg * 2) * 2);
                    *(u32*)(sm + KS_KHH + o0) = h01;
                    *(u32*)(sm + KS_KHH + o1) = h23;
                    *(u32*)(sm + KS_KHL + o0) = l01;
                    *(u32*)(sm + KS_KHL + o1) = l23;
                }
            }
            __syncthreads();
            // ---- z-mma: zT[80 vn][feat half] += vT @ k_hat ----
#pragma unroll
            for (int ks = 0; ks < 8; ks++) {
                u32 bh[2][2], bl[2][2];
#pragma unroll
                for (int j = 0; j < 2; j++) {
                    u32 la = (u32)((ks * 16 + (lane & 15)) * 272 + (w * 16 + j * 8) * 2);
                    ldmx2t(bh[j][0], bh[j][1], khh_u + la);
                    ldmx2t(bl[j][0], bl[j][1], khl_u + la);
                }
#pragma unroll
                for (int mt = 0; mt < 5; mt++) {
                    u32 ab = (u32)((mt * 16 + g) * 264 + ks * 32 + tg * 4);
                    u32 ah[4] = { *(u32*)(sm + KS_VTH + ab),      *(u32*)(sm + KS_VTH + ab + 8 * 264),
                                  *(u32*)(sm + KS_VTH + ab + 16), *(u32*)(sm + KS_VTH + ab + 8 * 264 + 16) };
                    u32 al[4] = { *(u32*)(sm + KS_VTL + ab),      *(u32*)(sm + KS_VTL + ab + 8 * 264),
                                  *(u32*)(sm + KS_VTL + ab + 16), *(u32*)(sm + KS_VTL + ab + 8 * 264 + 16) };
#pragma unroll
                    for (int j = 0; j < 2; j++) {
                        float* acc = zacc[mt][h * 2 + j];
                        mma_bf16(acc, ah, bh[j]);
                        mma_bf16(acc, ah, bl[j]);
                        mma_bf16(acc, al, bh[j]);
                    }
                }
            }
            __syncthreads();
        }
    }

    // flush zT accumulators
#pragma unroll
    for (int mt = 0; mt < 5; mt++) {
        int vn0 = mt * 16 + g, vn1 = vn0 + 8;
#pragma unroll
        for (int jj = 0; jj < 4; jj++) {
            int f0 = (jj >> 1) * 128 + w * 16 + (jj & 1) * 8 + tg * 2;
            if (vn0 < 65) {
                atomicAdd(&g_zT[vn0 * 256 + f0],     zacc[mt][jj][0]);
                atomicAdd(&g_zT[vn0 * 256 + f0 + 1], zacc[mt][jj][1]);
            }
            if (vn1 < 65) {
                atomicAdd(&g_zT[vn1 * 256 + f0],     zacc[mt][jj][2]);
                atomicAdd(&g_zT[vn1 * 256 + f0 + 1], zacc[mt][jj][3]);
            }
        }
    }
}

// ======================= qside =======================
// SMEM: Pt hi/lo [256][136], qn hi/lo [128][136], zT hi/lo [72][520], sn[128]
#define QS_PTH 0
#define QS_PTL 34816
#define QS_QNH 69632
#define QS_QNL 87040
#define QS_ZH  104448
#define QS_ZL  141888
#define QS_SN  179328
#define QSMEM  179840

__global__ __launch_bounds__(256, 1) void qside_kernel(
    const float* __restrict__ qin, const float* __restrict__ proj,
    float* __restrict__ out)
{
    extern __shared__ char sm[];
    const int tid = threadIdx.x;
    const int lane = tid & 31, w = tid >> 5;
    const int g = lane >> 2, tg = lane & 3;
    float* sn = reinterpret_cast<float*>(sm + QS_SN);

    stage64(sm + QS_PTH, sm + QS_PTL, proj, 256, 136, nullptr, tid);
    stage64(sm + QS_QNH, sm + QS_QNL, qin + (size_t)blockIdx.x * TILE * 64, 128, 136, sn, tid);
    // stage zT bf16 split into padded SMEM
    for (int i = tid; i < 72 * 128; i += 256) {
        int n = i >> 7, c = i & 127;
        *(u32*)(sm + QS_ZH + n * 520 + c * 4) = reinterpret_cast<const u32*>(g_zbh)[i];
        *(u32*)(sm + QS_ZL + n * 520 + c * 4) = reinterpret_cast<const u32*>(g_zbl)[i];
    }
    __syncthreads();

    // ---- dash: D[16 rows][256 feats] per warp ----
    float dD[32][4];
#pragma unroll
    for (int nt = 0; nt < 32; nt++)
#pragma unroll
        for (int r = 0; r < 4; r++) dD[nt][r] = 0.0f;
#pragma unroll
    for (int ks = 0; ks < 4; ks++) {
        u32 ab = (u32)((w * 16 + g) * 136 + ks * 32 + tg * 4);
        u32 ah[4] = { *(u32*)(sm + QS_QNH + ab),      *(u32*)(sm + QS_QNH + ab + 8 * 136),
                      *(u32*)(sm + QS_QNH + ab + 16), *(u32*)(sm + QS_QNH + ab + 8 * 136 + 16) };
        u32 al[4] = { *(u32*)(sm + QS_QNL + ab),      *(u32*)(sm + QS_QNL + ab + 8 * 136),
                      *(u32*)(sm + QS_QNL + ab + 16), *(u32*)(sm + QS_QNL + ab + 8 * 136 + 16) };
#pragma unroll
        for (int nt = 0; nt < 32; nt++) {
            u32 bb = (u32)((nt * 8 + g) * 136 + ks * 32 + tg * 4);
            u32 bh[2] = { *(u32*)(sm + QS_PTH + bb), *(u32*)(sm + QS_PTH + bb + 16) };
            u32 bl[2] = { *(u32*)(sm + QS_PTL + bb), *(u32*)(sm + QS_PTL + bb + 16) };
            mma_bf16(dD[nt], ah, bh);
            mma_bf16(dD[nt], ah, bl);
            mma_bf16(dD[nt], al, bh);
        }
    }

    // ---- epilogue: q_hat stays in registers as w-GEMM A-fragments ----
    u32 qh0[32], qh1[32], ql0[32], ql1[32];
    {
        float s0 = sn[w * 16 + g], s1 = sn[w * 16 + 8 + g];
#pragma unroll
        for (int nt = 0; nt < 32; nt++) {
            float e0 = RATIO * __expf(NORM * dD[nt][0] - 0.0625f * s0);
            float e1 = RATIO * __expf(NORM * dD[nt][1] - 0.0625f * s0);
            float e2 = RATIO * __expf(NORM * dD[nt][2] - 0.0625f * s1);
            float e3 = RATIO * __expf(NORM * dD[nt][3] - 0.0625f * s1);
            split2(e0, e1, qh0[nt], ql0[nt]);
            split2(e2, e3, qh1[nt], ql1[nt]);
        }
    }

    // ---- w-mma: D[16 rows][72] = q_hat @ zaug, K=256 ----
    float wD[9][4];
#pragma unroll
    for (int nt = 0; nt < 9; nt++)
#pragma unroll
        for (int r = 0; r < 4; r++) wD[nt][r] = 0.0f;
#pragma unroll
    for (int ks = 0; ks < 16; ks++) {
        u32 ah[4] = { qh0[2 * ks], qh1[2 * ks], qh0[2 * ks + 1], qh1[2 * ks + 1] };
        u32 al[4] = { ql0[2 * ks], ql1[2 * ks], ql0[2 * ks + 1], ql1[2 * ks + 1] };
#pragma unroll
        for (int nt = 0; nt < 9; nt++) {
            u32 bb = (u32)((nt * 8 + g) * 520 + ks * 32 + tg * 4);
            u32 bh[2] = { *(u32*)(sm + QS_ZH + bb), *(u32*)(sm + QS_ZH + bb + 16) };
            u32 bl[2] = { *(u32*)(sm + QS_ZL + bb), *(u32*)(sm + QS_ZL + bb + 16) };
            mma_bf16(wD[nt], ah, bh);
            mma_bf16(wD[nt], ah, bl);
            mma_bf16(wD[nt], al, bh);
        }
    }

    // ---- divide by denominator (col 64) and store ----
    float den0 = __shfl_sync(0xffffffffu, wD[8][0], lane & 0x1C);
    float den1 = __shfl_sync(0xffffffffu, wD[8][2], lane & 0x1C);
    float di0 = 1.0f / den0, di1 = 1.0f / den1;
    size_t row0 = (size_t)blockIdx.x * TILE + w * 16 + g;
    float* ob = out + row0 * 64 + tg * 2;
#pragma unroll
    for (int nt = 0; nt < 8; nt++) {
        *(float2*)(ob + nt * 8)          = make_float2(wD[nt][0] * di0, wD[nt][1] * di0);
        *(float2*)(ob + 8 * 64 + nt * 8) = make_float2(wD[nt][2] * di1, wD[nt][3] * di1);
    }
}

extern "C" void kernel_launch(void* const* d_in, const int* in_sizes, int n_in,
                              void* d_out, int out_size) {
    const float* q = (const float*)d_in[0];
    const float* k = (const float*)d_in[1];
    const float* v = (const float*)d_in[2];
    const float* P = (const float*)d_in[3];
    float* out = (float*)d_out;
    (void)in_sizes; (void)n_in; (void)out_size;

    cudaFuncSetAttribute(kside_kernel, cudaFuncAttributeMaxDynamicSharedMemorySize, KSMEM);
    cudaFuncSetAttribute(qside_kernel, cudaFuncAttributeMaxDynamicSharedMemorySize, QSMEM);

    zero_kernel<<<65, 256>>>();
    kside_kernel<<<KBLOCKS, 256, KSMEM>>>(k, v, P);
    zsplit_kernel<<<72, 256>>>();
    qside_kernel<<<NTILES, 256, QSMEM>>>(q, P, out);
}